// round 2
// baseline (speedup 1.0000x reference)
#include <cuda_runtime.h>
#include <cstdint>

#define E_DIM 2048
#define H_NUM 32
#define HD 64
#define B_NUM 16
#define T_NUM 4
#define P_LEN 4096
#define S_LEN 4100
#define M_ROWS 64
#define CH 128
#define NCH 32
#define NEG_MAX (-3.4028234663852886e38f)

// ---------------- scratch (device globals: no allocs allowed) ----------------
__device__ __align__(256) float g_q[M_ROWS * E_DIM];
__device__ __align__(256) float g_k[M_ROWS * E_DIM];
__device__ __align__(256) float g_v[M_ROWS * E_DIM];
__device__ __align__(256) float g_attn[M_ROWS * E_DIM];
__device__ __align__(256) float g_opart[H_NUM * NCH * M_ROWS * HD];
__device__ __align__(256) float g_pm[H_NUM * NCH * M_ROWS];
__device__ __align__(256) float g_pl[H_NUM * NCH * M_ROWS];

// ---------------- helpers ----------------
__device__ __forceinline__ uint32_t f2tf(float f) {
    uint32_t u;
    asm("cvt.rna.tf32.f32 %0, %1;" : "=r"(u) : "f"(f));
    return u;
}

__device__ __forceinline__ void mma_tf32(float* c, const uint32_t* a, uint32_t b0, uint32_t b1) {
    asm volatile(
        "mma.sync.aligned.m16n8k8.row.col.f32.tf32.tf32.f32 "
        "{%0,%1,%2,%3},{%4,%5,%6,%7},{%8,%9},{%0,%1,%2,%3};"
        : "+f"(c[0]), "+f"(c[1]), "+f"(c[2]), "+f"(c[3])
        : "r"(a[0]), "r"(a[1]), "r"(a[2]), "r"(a[3]), "r"(b0), "r"(b1));
}

// ---------------- projection GEMM: out[64, 2048] = A[64,2048] @ W[2048,2048]^T + b ----------------
// mode 0: blockIdx.y selects (Wq->g_q*scale, Wk->g_k, Wv->g_v), A = Aext (hidden)
// mode 1: A = g_attn, W0/B0 = Wo/bo, out = outext (d_out)
__global__ void __launch_bounds__(128) gemm_p(
    const float* __restrict__ Aext,
    const float* __restrict__ W0, const float* __restrict__ B0,
    const float* __restrict__ W1, const float* __restrict__ B1,
    const float* __restrict__ W2, const float* __restrict__ B2,
    float* __restrict__ outext, int mode)
{
    __shared__ uint32_t xs[M_ROWS * 36];   // A tile 64x32, stride 36 (conflict-free frags)
    __shared__ uint32_t wsm[32 * 36];      // W tile 32x32, stride 36

    const float* A;
    const float* W;
    const float* bias;
    float* out;
    float scale = 1.0f;
    if (mode == 1) {
        A = g_attn; W = W0; bias = B0; out = outext;
    } else {
        A = Aext;
        if (blockIdx.y == 0)      { W = W0; bias = B0; out = g_q; scale = 0.125f; }
        else if (blockIdx.y == 1) { W = W1; bias = B1; out = g_k; }
        else                      { W = W2; bias = B2; out = g_v; }
    }

    const int n_base = blockIdx.x * 32;
    const int tid = threadIdx.x;
    const int lane = tid & 31, wid = tid >> 5;
    const int m0 = (wid >> 1) * 32, n0 = (wid & 1) * 16;
    const int rb = lane >> 2, cq = lane & 3;

    float c[2][2][4];
#pragma unroll
    for (int i = 0; i < 2; i++)
#pragma unroll
        for (int j = 0; j < 2; j++)
#pragma unroll
            for (int k = 0; k < 4; k++) c[i][j][k] = 0.0f;

    float4 ra[4], rw[2];
#pragma unroll
    for (int i = 0; i < 4; i++) {
        int fi = tid + i * 128;
        ra[i] = *(const float4*)(A + (fi >> 3) * E_DIM + (fi & 7) * 4);
    }
#pragma unroll
    for (int i = 0; i < 2; i++) {
        int fi = tid + i * 128;
        rw[i] = *(const float4*)(W + (size_t)(n_base + (fi >> 3)) * E_DIM + (fi & 7) * 4);
    }

    for (int k0 = 0; k0 < E_DIM; k0 += 32) {
#pragma unroll
        for (int i = 0; i < 4; i++) {
            int fi = tid + i * 128;
            int base = (fi >> 3) * 36 + (fi & 7) * 4;
            xs[base + 0] = f2tf(ra[i].x); xs[base + 1] = f2tf(ra[i].y);
            xs[base + 2] = f2tf(ra[i].z); xs[base + 3] = f2tf(ra[i].w);
        }
#pragma unroll
        for (int i = 0; i < 2; i++) {
            int fi = tid + i * 128;
            int base = (fi >> 3) * 36 + (fi & 7) * 4;
            wsm[base + 0] = f2tf(rw[i].x); wsm[base + 1] = f2tf(rw[i].y);
            wsm[base + 2] = f2tf(rw[i].z); wsm[base + 3] = f2tf(rw[i].w);
        }
        __syncthreads();
        if (k0 + 32 < E_DIM) {
#pragma unroll
            for (int i = 0; i < 4; i++) {
                int fi = tid + i * 128;
                ra[i] = *(const float4*)(A + (fi >> 3) * E_DIM + (k0 + 32) + (fi & 7) * 4);
            }
#pragma unroll
            for (int i = 0; i < 2; i++) {
                int fi = tid + i * 128;
                rw[i] = *(const float4*)(W + (size_t)(n_base + (fi >> 3)) * E_DIM + (k0 + 32) + (fi & 7) * 4);
            }
        }
#pragma unroll
        for (int ks = 0; ks < 4; ks++) {
            int kk = ks * 8 + cq;
            uint32_t a[2][4], b[2][2];
#pragma unroll
            for (int mf = 0; mf < 2; mf++) {
                int r = m0 + mf * 16 + rb;
                a[mf][0] = xs[r * 36 + kk];
                a[mf][1] = xs[(r + 8) * 36 + kk];
                a[mf][2] = xs[r * 36 + kk + 4];
                a[mf][3] = xs[(r + 8) * 36 + kk + 4];
            }
#pragma unroll
            for (int nf = 0; nf < 2; nf++) {
                int nn = n0 + nf * 8 + rb;
                b[nf][0] = wsm[nn * 36 + kk];
                b[nf][1] = wsm[nn * 36 + kk + 4];
            }
#pragma unroll
            for (int mf = 0; mf < 2; mf++)
#pragma unroll
                for (int nf = 0; nf < 2; nf++)
                    mma_tf32(c[mf][nf], a[mf], b[nf][0], b[nf][1]);
        }
        __syncthreads();
    }

#pragma unroll
    for (int mf = 0; mf < 2; mf++) {
        int r0 = m0 + mf * 16 + rb;
#pragma unroll
        for (int nf = 0; nf < 2; nf++) {
            int cg = n_base + n0 + nf * 8 + cq * 2;
            out[r0 * E_DIM + cg]           = (c[mf][nf][0] + bias[cg]) * scale;
            out[r0 * E_DIM + cg + 1]       = (c[mf][nf][1] + bias[cg + 1]) * scale;
            out[(r0 + 8) * E_DIM + cg]     = (c[mf][nf][2] + bias[cg]) * scale;
            out[(r0 + 8) * E_DIM + cg + 1] = (c[mf][nf][3] + bias[cg + 1]) * scale;
        }
    }
}

// ---------------- attention over past cache, partial-softmax flash-decoding ----------------
// block = (chunk c of 128 past positions, head h); 64 query rows (= b*4+t) share K/V.
__global__ void __launch_bounds__(256) attn_part(
    const float* __restrict__ kpast, const float* __restrict__ vpast,
    const float* __restrict__ mask)
{
    extern __shared__ unsigned char smem_raw[];
    uint32_t* qs = (uint32_t*)smem_raw;          // [64][68] tf32
    uint32_t* ks = qs + 64 * 68;                 // [128][68] tf32
    float* ss = (float*)(ks + 128 * 68);         // [64][132] scores -> probs(tf32 bits)
    uint32_t* ssb = (uint32_t*)ss;
    uint32_t* vs = (uint32_t*)(ss + 64 * 132);   // [128][72] tf32

    const int cchunk = blockIdx.x;
    const int h = blockIdx.y;
    const int s0 = cchunk * CH;
    const int tid = threadIdx.x;
    const int lane = tid & 31, wid = tid >> 5;
    const int rb = lane >> 2, cq = lane & 3;

    // Q tile [64 x 64]
#pragma unroll
    for (int i = 0; i < 4; i++) {
        int fi = tid + i * 256;
        int m = fi >> 4, eq = fi & 15;
        float4 v = *(const float4*)(g_q + m * E_DIM + h * HD + eq * 4);
        int base = m * 68 + eq * 4;
        qs[base + 0] = f2tf(v.x); qs[base + 1] = f2tf(v.y);
        qs[base + 2] = f2tf(v.z); qs[base + 3] = f2tf(v.w);
    }
    // K chunk [128 x 64]
#pragma unroll
    for (int i = 0; i < 8; i++) {
        int fi = tid + i * 256;
        int s = fi >> 4, eq = fi & 15;
        float4 v = *(const float4*)(kpast + ((size_t)h * P_LEN + s0 + s) * HD + eq * 4);
        int base = s * 68 + eq * 4;
        ks[base + 0] = f2tf(v.x); ks[base + 1] = f2tf(v.y);
        ks[base + 2] = f2tf(v.z); ks[base + 3] = f2tf(v.w);
    }
    // issue V loads now; consumed after GEMM-S (latency hidden under compute)
    float4 vr[8];
#pragma unroll
    for (int i = 0; i < 8; i++) {
        int fi = tid + i * 256;
        int s = fi >> 4, eq = fi & 15;
        vr[i] = *(const float4*)(vpast + ((size_t)h * P_LEN + s0 + s) * HD + eq * 4);
    }
    __syncthreads();

    // GEMM-S: scores[64 x 128] = Q @ Kchunk^T ; warp wid owns 16 s-columns
    float c[4][2][4];
#pragma unroll
    for (int i = 0; i < 4; i++)
#pragma unroll
        for (int j = 0; j < 2; j++)
#pragma unroll
            for (int k = 0; k < 4; k++) c[i][j][k] = 0.0f;

    const int n0 = wid * 16;
#pragma unroll
    for (int kst = 0; kst < 8; kst++) {
        int kk = kst * 8 + cq;
        uint32_t a[4][4], b[2][2];
#pragma unroll
        for (int mf = 0; mf < 4; mf++) {
            int r = mf * 16 + rb;
            a[mf][0] = qs[r * 68 + kk];
            a[mf][1] = qs[(r + 8) * 68 + kk];
            a[mf][2] = qs[r * 68 + kk + 4];
            a[mf][3] = qs[(r + 8) * 68 + kk + 4];
        }
#pragma unroll
        for (int nf = 0; nf < 2; nf++) {
            int sc = n0 + nf * 8 + rb;
            b[nf][0] = ks[sc * 68 + kk];
            b[nf][1] = ks[sc * 68 + kk + 4];
        }
#pragma unroll
        for (int mf = 0; mf < 4; mf++)
#pragma unroll
            for (int nf = 0; nf < 2; nf++)
                mma_tf32(c[mf][nf], a[mf], b[nf][0], b[nf][1]);
    }

    // scores -> shared with mask add + clamp (mask row index = m = b*4+t directly)
#pragma unroll
    for (int mf = 0; mf < 4; mf++) {
        int r0 = mf * 16 + rb, r1 = r0 + 8;
#pragma unroll
        for (int nf = 0; nf < 2; nf++) {
            int col = n0 + nf * 8 + cq * 2;
            int sg = s0 + col;
            ss[r0 * 132 + col]     = fmaxf(c[mf][nf][0] + mask[r0 * S_LEN + sg], NEG_MAX);
            ss[r0 * 132 + col + 1] = fmaxf(c[mf][nf][1] + mask[r0 * S_LEN + sg + 1], NEG_MAX);
            ss[r1 * 132 + col]     = fmaxf(c[mf][nf][2] + mask[r1 * S_LEN + sg], NEG_MAX);
            ss[r1 * 132 + col + 1] = fmaxf(c[mf][nf][3] + mask[r1 * S_LEN + sg + 1], NEG_MAX);
        }
    }
    // V regs -> shared (tf32)
#pragma unroll
    for (int i = 0; i < 8; i++) {
        int fi = tid + i * 256;
        int s = fi >> 4, eq = fi & 15;
        int base = s * 72 + eq * 4;
        vs[base + 0] = f2tf(vr[i].x); vs[base + 1] = f2tf(vr[i].y);
        vs[base + 2] = f2tf(vr[i].z); vs[base + 3] = f2tf(vr[i].w);
    }
    __syncthreads();

    // partial softmax: warp handles 8 rows; lane covers 4 columns each
    float* pmp = g_pm + (size_t)(h * NCH + cchunk) * M_ROWS;
    float* plp = g_pl + (size_t)(h * NCH + cchunk) * M_ROWS;
#pragma unroll
    for (int rr = 0; rr < 8; rr++) {
        int r = wid * 8 + rr;
        int base = r * 132 + lane * 4;
        float v0 = ss[base], v1 = ss[base + 1], v2 = ss[base + 2], v3 = ss[base + 3];
        float mx = fmaxf(fmaxf(v0, v1), fmaxf(v2, v3));
#pragma unroll
        for (int off = 16; off > 0; off >>= 1)
            mx = fmaxf(mx, __shfl_xor_sync(0xffffffffu, mx, off));
        float p0 = __expf(v0 - mx), p1 = __expf(v1 - mx);
        float p2 = __expf(v2 - mx), p3 = __expf(v3 - mx);
        float sum = (p0 + p1) + (p2 + p3);
#pragma unroll
        for (int off = 16; off > 0; off >>= 1)
            sum += __shfl_xor_sync(0xffffffffu, sum, off);
        ssb[base] = f2tf(p0); ssb[base + 1] = f2tf(p1);
        ssb[base + 2] = f2tf(p2); ssb[base + 3] = f2tf(p3);
        if (lane == 0) { pmp[r] = mx; plp[r] = sum; }
    }
    __syncthreads();

    // GEMM-O: opart[64 x 64] = probs[64 x 128] @ V[128 x 64]; warp wid owns 8 d-columns
    float o[4][4];
#pragma unroll
    for (int i = 0; i < 4; i++)
#pragma unroll
        for (int j = 0; j < 4; j++) o[i][j] = 0.0f;

    const int d0 = wid * 8;
#pragma unroll
    for (int kst = 0; kst < 16; kst++) {
        int kk = kst * 8 + cq;
        uint32_t a[4][4];
#pragma unroll
        for (int mf = 0; mf < 4; mf++) {
            int r = mf * 16 + rb;
            a[mf][0] = ssb[r * 132 + kk];
            a[mf][1] = ssb[(r + 8) * 132 + kk];
            a[mf][2] = ssb[r * 132 + kk + 4];
            a[mf][3] = ssb[(r + 8) * 132 + kk + 4];
        }
        uint32_t b0 = vs[kk * 72 + d0 + rb];
        uint32_t b1 = vs[(kk + 4) * 72 + d0 + rb];
#pragma unroll
        for (int mf = 0; mf < 4; mf++)
            mma_tf32(o[mf], a[mf], b0, b1);
    }

    float* op = g_opart + (size_t)(h * NCH + cchunk) * M_ROWS * HD;
#pragma unroll
    for (int mf = 0; mf < 4; mf++) {
        int r0 = mf * 16 + rb;
        int cd = d0 + cq * 2;
        *(float2*)(op + r0 * HD + cd)       = make_float2(o[mf][0], o[mf][1]);
        *(float2*)(op + (r0 + 8) * HD + cd) = make_float2(o[mf][2], o[mf][3]);
    }
}

// ---------------- combine partials + the 4 batch-local new KV positions ----------------
// block = 256 threads = 4 rows x 64 d-lanes; grid 512 covers 2048 (h, m) rows.
__global__ void __launch_bounds__(256) attn_combine(const float* __restrict__ mask)
{
    __shared__ float red[4][4][2];
    __shared__ float shm[4][32], shl[4][32], ew[4][32], esn[4][4];

    const int tid = threadIdx.x;
    const int rg = tid >> 6, g = tid & 63;
    const int R = blockIdx.x * 4 + rg;
    const int h = R >> 6, m = R & 63;
    const int b = m >> 2;
    const int lane = tid & 31;
    const int whalf = (tid >> 5) & 1;

    // new scores: q_row . k_new[b, t'] (q already scaled)
    float qv = g_q[m * E_DIM + h * HD + g];
#pragma unroll
    for (int tp = 0; tp < 4; tp++) {
        float pv = qv * g_k[(b * 4 + tp) * E_DIM + h * HD + g];
#pragma unroll
        for (int off = 16; off > 0; off >>= 1)
            pv += __shfl_xor_sync(0xffffffffu, pv, off);
        if (lane == 0) red[rg][tp][whalf] = pv;
    }
    if (g < 32) {
        shm[rg][g] = g_pm[(size_t)(h * NCH + g) * M_ROWS + m];
        shl[rg][g] = g_pl[(size_t)(h * NCH + g) * M_ROWS + m];
    }
    __syncthreads();

    float sn[4];
#pragma unroll
    for (int tp = 0; tp < 4; tp++)
        sn[tp] = fmaxf(red[rg][tp][0] + red[rg][tp][1] + mask[m * S_LEN + P_LEN + tp], NEG_MAX);

    float M = NEG_MAX;
#pragma unroll
    for (int cc = 0; cc < 32; cc++) M = fmaxf(M, shm[rg][cc]);
#pragma unroll
    for (int tp = 0; tp < 4; tp++) M = fmaxf(M, sn[tp]);

    if (g < 32) ew[rg][g] = __expf(shm[rg][g] - M);
    if (g < 4)  esn[rg][g] = __expf(sn[g] - M);
    __syncthreads();

    float L = 0.0f;
#pragma unroll
    for (int cc = 0; cc < 32; cc++) L += shl[rg][cc] * ew[rg][cc];
#pragma unroll
    for (int tp = 0; tp < 4; tp++) L += esn[rg][tp];

    float o = 0.0f;
#pragma unroll 8
    for (int cc = 0; cc < 32; cc++)
        o += g_opart[((size_t)(h * NCH + cc) * M_ROWS + m) * HD + g] * ew[rg][cc];
#pragma unroll
    for (int tp = 0; tp < 4; tp++)
        o += esn[rg][tp] * g_v[(b * 4 + tp) * E_DIM + h * HD + g];

    g_attn[m * E_DIM + h * HD + g] = o / L;
}

// ---------------- launch ----------------
extern "C" void kernel_launch(void* const* d_in, const int* in_sizes, int n_in,
                              void* d_out, int out_size)
{
    const float* hs   = (const float*)d_in[0];
    const float* pk   = (const float*)d_in[1];
    const float* pv   = (const float*)d_in[2];
    const float* mask = (const float*)d_in[3];
    const float* Wq   = (const float*)d_in[4];
    const float* bq   = (const float*)d_in[5];
    const float* Wk   = (const float*)d_in[6];
    const float* bk   = (const float*)d_in[7];
    const float* Wv   = (const float*)d_in[8];
    const float* bv   = (const float*)d_in[9];
    const float* Wo   = (const float*)d_in[10];
    const float* bo   = (const float*)d_in[11];
    float* out = (float*)d_out;

    const int attn_smem = (64 * 68 + 128 * 68 + 64 * 132 + 128 * 72) * 4; // 122880 B
    cudaFuncSetAttribute(attn_part, cudaFuncAttributeMaxDynamicSharedMemorySize, attn_smem);

    // QKV projections (fused in one grid)
    gemm_p<<<dim3(64, 3), 128>>>(hs, Wq, bq, Wk, bk, Wv, bv, nullptr, 0);
    // attention over past cache (flash-decoding partials)
    attn_part<<<dim3(NCH, H_NUM), 256, attn_smem>>>(pk, pv, mask);
    // merge partials + new-token KV
    attn_combine<<<512, 256>>>(mask);
    // output projection -> d_out
    gemm_p<<<dim3(64, 1), 128>>>(nullptr, Wo, bo, nullptr, nullptr, nullptr, nullptr, out, 1);
}

// round 3
// speedup vs baseline: 1.9954x; 1.9954x over previous
#include <cuda_runtime.h>
#include <cstdint>

#define E_DIM 2048
#define H_NUM 32
#define HD 64
#define P_LEN 4096
#define S_LEN 4100
#define M_ROWS 64
#define CH 128
#define NCH 32
#define NEG_MAX (-3.4028234663852886e38f)

// ---------------- scratch (device globals: no allocs allowed) ----------------
__device__ __align__(256) float g_q[M_ROWS * E_DIM];
__device__ __align__(256) float g_k[M_ROWS * E_DIM];
__device__ __align__(256) float g_v[M_ROWS * E_DIM];
__device__ __align__(256) float g_attn[M_ROWS * E_DIM];
__device__ __align__(256) float g_opart[H_NUM * NCH * M_ROWS * HD];
__device__ __align__(256) float g_pm[H_NUM * NCH * M_ROWS];
__device__ __align__(256) float g_pl[H_NUM * NCH * M_ROWS];

// ---------------- helpers ----------------
__device__ __forceinline__ uint32_t f2tf(float f) {
    uint32_t u;
    asm("cvt.rna.tf32.f32 %0, %1;" : "=r"(u) : "f"(f));
    return u;
}

__device__ __forceinline__ void mma_tf32(float* c, const uint32_t* a, uint32_t b0, uint32_t b1) {
    asm volatile(
        "mma.sync.aligned.m16n8k8.row.col.f32.tf32.tf32.f32 "
        "{%0,%1,%2,%3},{%4,%5,%6,%7},{%8,%9},{%0,%1,%2,%3};"
        : "+f"(c[0]), "+f"(c[1]), "+f"(c[2]), "+f"(c[3])
        : "r"(a[0]), "r"(a[1]), "r"(a[2]), "r"(a[3]), "r"(b0), "r"(b1));
}

__device__ __forceinline__ void cp16(float* smem_dst, const float* gsrc) {
    uint32_t s = (uint32_t)__cvta_generic_to_shared(smem_dst);
    asm volatile("cp.async.cg.shared.global [%0], [%1], 16;" :: "r"(s), "l"(gsrc));
}
__device__ __forceinline__ void cp_commit() {
    asm volatile("cp.async.commit_group;");
}
template<int N> __device__ __forceinline__ void cp_wait() {
    asm volatile("cp.async.wait_group %0;" :: "n"(N));
}

// ---------------- pipelined projection GEMM ----------------
// out[64, 2048] = A[64,2048] @ W[2048,2048]^T + bias, tile 64 x NT, K-step 32, 4 stages.
// mode 0: blockIdx.y selects (Wq->g_q*0.125, Wk->g_k, Wv->g_v), A = Aext
// mode 1: A = g_attn, W0/B0 = Wo/bo, out = outext
template<int NT>
__global__ void __launch_bounds__(256) gemm_t(
    const float* __restrict__ Aext,
    const float* __restrict__ W0, const float* __restrict__ B0,
    const float* __restrict__ W1, const float* __restrict__ B1,
    const float* __restrict__ W2, const float* __restrict__ B2,
    float* __restrict__ outext, int mode)
{
    extern __shared__ float sm[];
    const int STAGE = (64 + NT) * 36;

    const float* A;
    const float* W;
    const float* bias;
    float* out;
    float scale = 1.0f;
    if (mode == 1) {
        A = g_attn; W = W0; bias = B0; out = outext;
    } else {
        A = Aext;
        if (blockIdx.y == 0)      { W = W0; bias = B0; out = g_q; scale = 0.125f; }
        else if (blockIdx.y == 1) { W = W1; bias = B1; out = g_k; }
        else                      { W = W2; bias = B2; out = g_v; }
    }

    const int n_base = blockIdx.x * NT;
    const int tid = threadIdx.x;
    const int lane = tid & 31, wid = tid >> 5;
    const int rb = lane >> 2, cq = lane & 3;
    const int m0 = (wid >> 1) * 16;
    const int NFR = NT / 16;              // 2 for NT=32, 1 for NT=16
    const int n0 = (wid & 1) * (NT / 2);  // 16 or 8

    float c[2][4];
#pragma unroll
    for (int j = 0; j < 2; j++)
#pragma unroll
        for (int k = 0; k < 4; k++) c[j][k] = 0.0f;

    // stage loader
    auto load_stage = [&](int buf, int k0) {
        float* Asb = sm + buf * STAGE;
        float* Wsb = Asb + 64 * 36;
#pragma unroll
        for (int i = 0; i < 2; i++) {
            int cc = tid + i * 256;
            int row = cc >> 3, kc = cc & 7;
            cp16(Asb + row * 36 + kc * 4, A + row * E_DIM + k0 + kc * 4);
        }
        if (NT == 32) {
            int row = tid >> 3, kc = tid & 7;
            cp16(Wsb + row * 36 + kc * 4, W + (size_t)(n_base + row) * E_DIM + k0 + kc * 4);
        } else {
            if (tid < 128) {
                int row = tid >> 3, kc = tid & 7;
                cp16(Wsb + row * 36 + kc * 4, W + (size_t)(n_base + row) * E_DIM + k0 + kc * 4);
            }
        }
    };

#pragma unroll
    for (int s = 0; s < 3; s++) { load_stage(s, s * 32); cp_commit(); }

    const int NITER = E_DIM / 32;  // 64
    for (int it = 0; it < NITER; it++) {
        cp_wait<2>();
        __syncthreads();
        float* Asb = sm + (it & 3) * STAGE;
        float* Wsb = Asb + 64 * 36;
#pragma unroll
        for (int ks = 0; ks < 4; ks++) {
            int kk = ks * 8 + cq;
            uint32_t a[4];
            a[0] = f2tf(Asb[(m0 + rb) * 36 + kk]);
            a[1] = f2tf(Asb[(m0 + 8 + rb) * 36 + kk]);
            a[2] = f2tf(Asb[(m0 + rb) * 36 + kk + 4]);
            a[3] = f2tf(Asb[(m0 + 8 + rb) * 36 + kk + 4]);
#pragma unroll
            for (int nf = 0; nf < NFR; nf++) {
                int nn = n0 + nf * 8 + rb;
                uint32_t b0 = f2tf(Wsb[nn * 36 + kk]);
                uint32_t b1 = f2tf(Wsb[nn * 36 + kk + 4]);
                mma_tf32(c[nf], a, b0, b1);
            }
        }
        int nx = it + 3;
        if (nx < NITER) load_stage(nx & 3, nx * 32);
        cp_commit();
    }

#pragma unroll
    for (int nf = 0; nf < NFR; nf++) {
        int cg = n_base + n0 + nf * 8 + cq * 2;
        int r0 = m0 + rb;
        out[r0 * E_DIM + cg]           = (c[nf][0] + bias[cg]) * scale;
        out[r0 * E_DIM + cg + 1]       = (c[nf][1] + bias[cg + 1]) * scale;
        out[(r0 + 8) * E_DIM + cg]     = (c[nf][2] + bias[cg]) * scale;
        out[(r0 + 8) * E_DIM + cg + 1] = (c[nf][3] + bias[cg + 1]) * scale;
    }
}

// ---------------- attention over past cache, partial-softmax flash-decoding ----------------
// block = (chunk c of 128 past positions, head h); 64 query rows (= b*4+t) share K/V.
// smem: fp32 Q[64][68] + K[128][68] + V[128][72]; score buffer aliases Q+K after GEMM-S.
__global__ void __launch_bounds__(256) attn_part(
    const float* __restrict__ kpast, const float* __restrict__ vpast,
    const float* __restrict__ mask)
{
    extern __shared__ float sm[];
    float* qs = sm;                  // [64][68]
    float* ks = qs + 64 * 68;        // [128][68]
    float* vs = ks + 128 * 68;       // [128][72]
    float* ss = qs;                  // alias [64][132] over qs+ks (8448 <= 13056 floats)
    uint32_t* ssb = (uint32_t*)ss;

    const int cchunk = blockIdx.x;
    const int h = blockIdx.y;
    const int s0 = cchunk * CH;
    const int tid = threadIdx.x;
    const int lane = tid & 31, wid = tid >> 5;
    const int rb = lane >> 2, cq = lane & 3;

    // async loads: Q (16KB) + K (32KB) in group 0, V (32KB) in group 1
#pragma unroll
    for (int i = 0; i < 4; i++) {
        int cc = tid + i * 256;
        int m = cc >> 4, kc = cc & 15;
        cp16(qs + m * 68 + kc * 4, g_q + m * E_DIM + h * HD + kc * 4);
    }
#pragma unroll
    for (int i = 0; i < 8; i++) {
        int cc = tid + i * 256;
        int s = cc >> 4, kc = cc & 15;
        cp16(ks + s * 68 + kc * 4, kpast + ((size_t)h * P_LEN + s0 + s) * HD + kc * 4);
    }
    cp_commit();
#pragma unroll
    for (int i = 0; i < 8; i++) {
        int cc = tid + i * 256;
        int s = cc >> 4, kc = cc & 15;
        cp16(vs + s * 72 + kc * 4, vpast + ((size_t)h * P_LEN + s0 + s) * HD + kc * 4);
    }
    cp_commit();

    cp_wait<1>();
    __syncthreads();

    // GEMM-S: scores[64 x 128] = Q @ Kchunk^T ; warp wid owns 16 s-columns
    float c[4][2][4];
#pragma unroll
    for (int i = 0; i < 4; i++)
#pragma unroll
        for (int j = 0; j < 2; j++)
#pragma unroll
            for (int k = 0; k < 4; k++) c[i][j][k] = 0.0f;

    const int n0 = wid * 16;
#pragma unroll
    for (int kst = 0; kst < 8; kst++) {
        int kk = kst * 8 + cq;
        uint32_t a[4][4], b[2][2];
#pragma unroll
        for (int mf = 0; mf < 4; mf++) {
            int r = mf * 16 + rb;
            a[mf][0] = f2tf(qs[r * 68 + kk]);
            a[mf][1] = f2tf(qs[(r + 8) * 68 + kk]);
            a[mf][2] = f2tf(qs[r * 68 + kk + 4]);
            a[mf][3] = f2tf(qs[(r + 8) * 68 + kk + 4]);
        }
#pragma unroll
        for (int nf = 0; nf < 2; nf++) {
            int sc = n0 + nf * 8 + rb;
            b[nf][0] = f2tf(ks[sc * 68 + kk]);
            b[nf][1] = f2tf(ks[sc * 68 + kk + 4]);
        }
#pragma unroll
        for (int mf = 0; mf < 4; mf++)
#pragma unroll
            for (int nf = 0; nf < 2; nf++)
                mma_tf32(c[mf][nf], a[mf], b[nf][0], b[nf][1]);
    }

    cp_wait<0>();       // V resident
    __syncthreads();    // all warps done reading qs/ks -> safe to alias ss

    // scores -> ss with mask add + clamp (mask row index = m = b*4+t directly)
#pragma unroll
    for (int mf = 0; mf < 4; mf++) {
        int r0 = mf * 16 + rb, r1 = r0 + 8;
#pragma unroll
        for (int nf = 0; nf < 2; nf++) {
            int col = n0 + nf * 8 + cq * 2;
            int sg = s0 + col;
            ss[r0 * 132 + col]     = fmaxf(c[mf][nf][0] + mask[r0 * S_LEN + sg], NEG_MAX);
            ss[r0 * 132 + col + 1] = fmaxf(c[mf][nf][1] + mask[r0 * S_LEN + sg + 1], NEG_MAX);
            ss[r1 * 132 + col]     = fmaxf(c[mf][nf][2] + mask[r1 * S_LEN + sg], NEG_MAX);
            ss[r1 * 132 + col + 1] = fmaxf(c[mf][nf][3] + mask[r1 * S_LEN + sg + 1], NEG_MAX);
        }
    }
    __syncthreads();

    // partial softmax: warp handles 8 rows; lane covers 4 columns each
    float* pmp = g_pm + (size_t)(h * NCH + cchunk) * M_ROWS;
    float* plp = g_pl + (size_t)(h * NCH + cchunk) * M_ROWS;
#pragma unroll
    for (int rr = 0; rr < 8; rr++) {
        int r = wid * 8 + rr;
        int base = r * 132 + lane * 4;
        float v0 = ss[base], v1 = ss[base + 1], v2 = ss[base + 2], v3 = ss[base + 3];
        float mx = fmaxf(fmaxf(v0, v1), fmaxf(v2, v3));
#pragma unroll
        for (int off = 16; off > 0; off >>= 1)
            mx = fmaxf(mx, __shfl_xor_sync(0xffffffffu, mx, off));
        float p0 = __expf(v0 - mx), p1 = __expf(v1 - mx);
        float p2 = __expf(v2 - mx), p3 = __expf(v3 - mx);
        float sum = (p0 + p1) + (p2 + p3);
#pragma unroll
        for (int off = 16; off > 0; off >>= 1)
            sum += __shfl_xor_sync(0xffffffffu, sum, off);
        ssb[base] = f2tf(p0); ssb[base + 1] = f2tf(p1);
        ssb[base + 2] = f2tf(p2); ssb[base + 3] = f2tf(p3);
        if (lane == 0) { pmp[r] = mx; plp[r] = sum; }
    }
    __syncthreads();

    // GEMM-O: opart[64 x 64] = probs[64 x 128] @ V[128 x 64]; warp wid owns 8 d-columns
    float o[4][4];
#pragma unroll
    for (int i = 0; i < 4; i++)
#pragma unroll
        for (int j = 0; j < 4; j++) o[i][j] = 0.0f;

    const int d0 = wid * 8;
#pragma unroll
    for (int kst = 0; kst < 16; kst++) {
        int kk = kst * 8 + cq;
        uint32_t a[4][4];
#pragma unroll
        for (int mf = 0; mf < 4; mf++) {
            int r = mf * 16 + rb;
            a[mf][0] = ssb[r * 132 + kk];
            a[mf][1] = ssb[(r + 8) * 132 + kk];
            a[mf][2] = ssb[r * 132 + kk + 4];
            a[mf][3] = ssb[(r + 8) * 132 + kk + 4];
        }
        uint32_t b0 = f2tf(vs[kk * 72 + d0 + rb]);
        uint32_t b1 = f2tf(vs[(kk + 4) * 72 + d0 + rb]);
#pragma unroll
        for (int mf = 0; mf < 4; mf++)
            mma_tf32(o[mf], a[mf], b0, b1);
    }

    float* op = g_opart + (size_t)(h * NCH + cchunk) * M_ROWS * HD;
#pragma unroll
    for (int mf = 0; mf < 4; mf++) {
        int r0 = mf * 16 + rb;
        int cd = d0 + cq * 2;
        *(float2*)(op + r0 * HD + cd)       = make_float2(o[mf][0], o[mf][1]);
        *(float2*)(op + (r0 + 8) * HD + cd) = make_float2(o[mf][2], o[mf][3]);
    }
}

// ---------------- combine partials + the 4 batch-local new KV positions ----------------
// block = 256 threads = 4 rows x 64 d-lanes; grid 512 covers 2048 (h, m) rows.
__global__ void __launch_bounds__(256) attn_combine(const float* __restrict__ mask)
{
    __shared__ float red[4][4][2];
    __shared__ float shm[4][32], shl[4][32], ew[4][32], esn[4][4];

    const int tid = threadIdx.x;
    const int rg = tid >> 6, g = tid & 63;
    const int R = blockIdx.x * 4 + rg;
    const int h = R >> 6, m = R & 63;
    const int b = m >> 2;
    const int lane = tid & 31;
    const int whalf = (tid >> 5) & 1;

    // new scores: q_row . k_new[b, t'] (q already scaled)
    float qv = g_q[m * E_DIM + h * HD + g];
#pragma unroll
    for (int tp = 0; tp < 4; tp++) {
        float pv = qv * g_k[(b * 4 + tp) * E_DIM + h * HD + g];
#pragma unroll
        for (int off = 16; off > 0; off >>= 1)
            pv += __shfl_xor_sync(0xffffffffu, pv, off);
        if (lane == 0) red[rg][tp][whalf] = pv;
    }
    if (g < 32) {
        shm[rg][g] = g_pm[(size_t)(h * NCH + g) * M_ROWS + m];
        shl[rg][g] = g_pl[(size_t)(h * NCH + g) * M_ROWS + m];
    }
    __syncthreads();

    float sn[4];
#pragma unroll
    for (int tp = 0; tp < 4; tp++)
        sn[tp] = fmaxf(red[rg][tp][0] + red[rg][tp][1] + mask[m * S_LEN + P_LEN + tp], NEG_MAX);

    float M = NEG_MAX;
#pragma unroll
    for (int cc = 0; cc < 32; cc++) M = fmaxf(M, shm[rg][cc]);
#pragma unroll
    for (int tp = 0; tp < 4; tp++) M = fmaxf(M, sn[tp]);

    if (g < 32) ew[rg][g] = __expf(shm[rg][g] - M);
    if (g < 4)  esn[rg][g] = __expf(sn[g] - M);
    __syncthreads();

    float L = 0.0f;
#pragma unroll
    for (int cc = 0; cc < 32; cc++) L += shl[rg][cc] * ew[rg][cc];
#pragma unroll
    for (int tp = 0; tp < 4; tp++) L += esn[rg][tp];

    float o = 0.0f;
#pragma unroll 8
    for (int cc = 0; cc < 32; cc++)
        o += g_opart[((size_t)(h * NCH + cc) * M_ROWS + m) * HD + g] * ew[rg][cc];
#pragma unroll
    for (int tp = 0; tp < 4; tp++)
        o += esn[rg][tp] * g_v[(b * 4 + tp) * E_DIM + h * HD + g];

    g_attn[m * E_DIM + h * HD + g] = o / L;
}

// ---------------- launch ----------------
extern "C" void kernel_launch(void* const* d_in, const int* in_sizes, int n_in,
                              void* d_out, int out_size)
{
    const float* hs   = (const float*)d_in[0];
    const float* pk   = (const float*)d_in[1];
    const float* pv   = (const float*)d_in[2];
    const float* mask = (const float*)d_in[3];
    const float* Wq   = (const float*)d_in[4];
    const float* bq   = (const float*)d_in[5];
    const float* Wk   = (const float*)d_in[6];
    const float* bk   = (const float*)d_in[7];
    const float* Wv   = (const float*)d_in[8];
    const float* bv   = (const float*)d_in[9];
    const float* Wo   = (const float*)d_in[10];
    const float* bo   = (const float*)d_in[11];
    float* out = (float*)d_out;

    const int smem32 = 4 * (64 + 32) * 36 * 4;  // 55296
    const int smem16 = 4 * (64 + 16) * 36 * 4;  // 46080
    const int attn_smem = (64 * 68 + 128 * 68 + 128 * 72) * 4;  // 89088

    cudaFuncSetAttribute(gemm_t<32>, cudaFuncAttributeMaxDynamicSharedMemorySize, smem32);
    cudaFuncSetAttribute(gemm_t<16>, cudaFuncAttributeMaxDynamicSharedMemorySize, smem16);
    cudaFuncSetAttribute(attn_part, cudaFuncAttributeMaxDynamicSharedMemorySize, attn_smem);

    // QKV projections (fused in one grid)
    gemm_t<32><<<dim3(64, 3), 256, smem32>>>(hs, Wq, bq, Wk, bk, Wv, bv, nullptr, 0);
    // attention over past cache (flash-decoding partials)
    attn_part<<<dim3(NCH, H_NUM), 256, attn_smem>>>(pk, pv, mask);
    // merge partials + new-token KV
    attn_combine<<<512, 256>>>(mask);
    // output projection -> d_out (128 blocks, N-tile 16)
    gemm_t<16><<<dim3(128, 1), 256, smem16>>>(nullptr, Wo, bo, nullptr, nullptr, nullptr, nullptr, out, 1);
}

// round 5
// speedup vs baseline: 2.3413x; 1.1734x over previous
#include <cuda_runtime.h>
#include <cstdint>

#define E_DIM 2048
#define H_NUM 32
#define HD 64
#define P_LEN 4096
#define S_LEN 4100
#define M_ROWS 64
#define CH 128
#define NCH 32
#define NEG_MAX (-3.4028234663852886e38f)

// ---------------- scratch (device globals: no allocs allowed) ----------------
__device__ __align__(256) float g_q[M_ROWS * E_DIM];
__device__ __align__(256) float g_k[M_ROWS * E_DIM];
__device__ __align__(256) float g_v[M_ROWS * E_DIM];
__device__ __align__(256) float g_attn[M_ROWS * E_DIM];
__device__ __align__(256) float g_opart[H_NUM * NCH * M_ROWS * HD];
__device__ __align__(256) float g_pm[H_NUM * NCH * M_ROWS];
__device__ __align__(256) float g_pl[H_NUM * NCH * M_ROWS];
__device__ __align__(256) float g_pp[6 * M_ROWS * E_DIM];   // split-K partials

// ---------------- helpers ----------------
__device__ __forceinline__ uint32_t f2tf(float f) {
    uint32_t u;
    asm("cvt.rna.tf32.f32 %0, %1;" : "=r"(u) : "f"(f));
    return u;
}

__device__ __forceinline__ void mma_tf32(float* c, const uint32_t* a, uint32_t b0, uint32_t b1) {
    asm volatile(
        "mma.sync.aligned.m16n8k8.row.col.f32.tf32.tf32.f32 "
        "{%0,%1,%2,%3},{%4,%5,%6,%7},{%8,%9},{%0,%1,%2,%3};"
        : "+f"(c[0]), "+f"(c[1]), "+f"(c[2]), "+f"(c[3])
        : "r"(a[0]), "r"(a[1]), "r"(a[2]), "r"(a[3]), "r"(b0), "r"(b1));
}

__device__ __forceinline__ void cp16(float* smem_dst, const float* gsrc) {
    uint32_t s = (uint32_t)__cvta_generic_to_shared(smem_dst);
    asm volatile("cp.async.cg.shared.global [%0], [%1], 16;" :: "r"(s), "l"(gsrc));
}
__device__ __forceinline__ void cp_commit() {
    asm volatile("cp.async.commit_group;");
}
template<int N> __device__ __forceinline__ void cp_wait() {
    asm volatile("cp.async.wait_group %0;" :: "n"(N));
}

// ---------------- W-major split-K projection GEMM ----------------
// C[f, t] = sum_k W[f,k] * A[t,k]; W is the mma A-operand, tokens the B-operand.
// grid: (feature_tiles=32, n_mats, ksplit). partial slot = z*gridDim.y + y.
// A == nullptr selects g_attn (device-side; __device__ symbols can't be passed from host).
__global__ void __launch_bounds__(256) gemm_w(
    const float* __restrict__ A,
    const float* __restrict__ W0, const float* __restrict__ W1, const float* __restrict__ W2,
    int kspan)
{
    extern __shared__ float sm[];
    const int STAGE = 128 * 36;

    if (A == nullptr) A = g_attn;
    const float* W = (blockIdx.y == 0) ? W0 : (blockIdx.y == 1) ? W1 : W2;
    const int fbase = blockIdx.x * 64;
    const int k0 = blockIdx.z * kspan;
    float* part = g_pp + (size_t)(blockIdx.z * gridDim.y + blockIdx.y) * (M_ROWS * E_DIM);

    const int tid = threadIdx.x;
    const int lane = tid & 31, wid = tid >> 5;
    const int rb = lane >> 2, cq = lane & 3;
    const int m0 = (wid >> 1) * 16;     // feature sub-tile
    const int n0 = (wid & 1) * 32;      // token sub-tile

    float c[4][4];
#pragma unroll
    for (int i = 0; i < 4; i++)
#pragma unroll
        for (int j = 0; j < 4; j++) c[i][j] = 0.0f;

    auto load_stage = [&](int buf, int kk0) {
        float* ws = sm + buf * STAGE;
        float* as = ws + 64 * 36;
        int row = tid >> 3, kc = tid & 7;
        cp16(ws + row * 36 + kc * 4,        W + (size_t)(fbase + row) * E_DIM + kk0 + kc * 4);
        cp16(ws + (row + 32) * 36 + kc * 4, W + (size_t)(fbase + row + 32) * E_DIM + kk0 + kc * 4);
        cp16(as + row * 36 + kc * 4,        A + (row) * E_DIM + kk0 + kc * 4);
        cp16(as + (row + 32) * 36 + kc * 4, A + (row + 32) * E_DIM + kk0 + kc * 4);
    };

#pragma unroll
    for (int s = 0; s < 3; s++) { load_stage(s, k0 + s * 32); cp_commit(); }

    const int NITER = kspan / 32;
    for (int it = 0; it < NITER; it++) {
        cp_wait<2>();
        __syncthreads();
        float* ws = sm + (it & 3) * STAGE;
        float* as = ws + 64 * 36;
#pragma unroll
        for (int ks = 0; ks < 4; ks++) {
            int kk = ks * 8 + cq;
            uint32_t a[4];
            a[0] = f2tf(ws[(m0 + rb) * 36 + kk]);
            a[1] = f2tf(ws[(m0 + 8 + rb) * 36 + kk]);
            a[2] = f2tf(ws[(m0 + rb) * 36 + kk + 4]);
            a[3] = f2tf(ws[(m0 + 8 + rb) * 36 + kk + 4]);
#pragma unroll
            for (int nf = 0; nf < 4; nf++) {
                int nn = n0 + nf * 8 + rb;
                uint32_t b0 = f2tf(as[nn * 36 + kk]);
                uint32_t b1 = f2tf(as[nn * 36 + kk + 4]);
                mma_tf32(c[nf], a, b0, b1);
            }
        }
        int nx = it + 3;
        if (nx < NITER) load_stage(nx & 3, k0 + nx * 32);
        cp_commit();
    }

    const int f = fbase + m0 + rb;
#pragma unroll
    for (int nf = 0; nf < 4; nf++) {
        int t0 = n0 + nf * 8 + cq * 2;
        part[t0 * E_DIM + f]           = c[nf][0];
        part[(t0 + 1) * E_DIM + f]     = c[nf][1];
        part[t0 * E_DIM + f + 8]       = c[nf][2];
        part[(t0 + 1) * E_DIM + f + 8] = c[nf][3];
    }
}

// ---------------- reduce split-K partials ----------------
// QKV: slots {mat, mat+3}, add bias, scale Q by 0.125. grid 384x256 (float4 granularity)
__global__ void __launch_bounds__(256) reduce_qkv(
    const float* __restrict__ bq, const float* __restrict__ bk, const float* __restrict__ bv)
{
    int gid = blockIdx.x * 256 + threadIdx.x;    // 0..98303
    int mat = gid >> 15;
    int r = gid & 32767;
    int f4 = r & 511;
    float4 a = ((const float4*)g_pp)[(size_t)mat * 32768 + r];
    float4 b = ((const float4*)g_pp)[(size_t)(mat + 3) * 32768 + r];
    const float* bias = (mat == 0) ? bq : (mat == 1) ? bk : bv;
    float4 bb = ((const float4*)bias)[f4];
    float s = (mat == 0) ? 0.125f : 1.0f;
    float4 o;
    o.x = (a.x + b.x + bb.x) * s;
    o.y = (a.y + b.y + bb.y) * s;
    o.z = (a.z + b.z + bb.z) * s;
    o.w = (a.w + b.w + bb.w) * s;
    float* out = (mat == 0) ? g_q : (mat == 1) ? g_k : g_v;
    ((float4*)out)[r] = o;
}

// O-proj: slots 0..3, add bias, write d_out. grid 128x256
__global__ void __launch_bounds__(256) reduce_o(const float* __restrict__ bo, float* __restrict__ out)
{
    int r = blockIdx.x * 256 + threadIdx.x;      // 0..32767
    int f4 = r & 511;
    float4 a = ((const float4*)g_pp)[r];
    float4 b = ((const float4*)g_pp)[32768 + r];
    float4 c = ((const float4*)g_pp)[65536 + r];
    float4 d = ((const float4*)g_pp)[98304 + r];
    float4 bb = ((const float4*)bo)[f4];
    float4 o;
    o.x = a.x + b.x + c.x + d.x + bb.x;
    o.y = a.y + b.y + c.y + d.y + bb.y;
    o.z = a.z + b.z + c.z + d.z + bb.z;
    o.w = a.w + b.w + c.w + d.w + bb.w;
    ((float4*)out)[r] = o;
}

// ---------------- attention over past cache, partial-softmax flash-decoding ----------------
__global__ void __launch_bounds__(256, 2) attn_part(
    const float* __restrict__ kpast, const float* __restrict__ vpast,
    const float* __restrict__ mask)
{
    extern __shared__ float sm[];
    float* qs = sm;                  // [64][68]
    float* ks = qs + 64 * 68;        // [128][68]
    float* vs = ks + 128 * 68;       // [128][72]
    float* ss = qs;                  // alias [64][132] over qs+ks
    uint32_t* ssb = (uint32_t*)ss;

    const int cchunk = blockIdx.x;
    const int h = blockIdx.y;
    const int s0 = cchunk * CH;
    const int tid = threadIdx.x;
    const int lane = tid & 31, wid = tid >> 5;
    const int rb = lane >> 2, cq = lane & 3;
    const int n0 = wid * 16;

    // async loads: Q+K group 0, V group 1
#pragma unroll
    for (int i = 0; i < 4; i++) {
        int cc = tid + i * 256;
        int m = cc >> 4, kc = cc & 15;
        cp16(qs + m * 68 + kc * 4, g_q + m * E_DIM + h * HD + kc * 4);
    }
#pragma unroll
    for (int i = 0; i < 8; i++) {
        int cc = tid + i * 256;
        int s = cc >> 4, kc = cc & 15;
        cp16(ks + s * 68 + kc * 4, kpast + ((size_t)h * P_LEN + s0 + s) * HD + kc * 4);
    }
    cp_commit();
#pragma unroll
    for (int i = 0; i < 8; i++) {
        int cc = tid + i * 256;
        int s = cc >> 4, kc = cc & 15;
        cp16(vs + s * 72 + kc * 4, vpast + ((size_t)h * P_LEN + s0 + s) * HD + kc * 4);
    }
    cp_commit();

    // prefetch this thread's 16 mask values (consumed after GEMM-S; hides L2 latency)
    float2 mk0[4][2], mk1[4][2];
#pragma unroll
    for (int mf = 0; mf < 4; mf++) {
        int r0 = mf * 16 + rb, r1 = r0 + 8;
#pragma unroll
        for (int nf = 0; nf < 2; nf++) {
            int sg = s0 + n0 + nf * 8 + cq * 2;
            mk0[mf][nf] = *(const float2*)(mask + r0 * S_LEN + sg);
            mk1[mf][nf] = *(const float2*)(mask + r1 * S_LEN + sg);
        }
    }

    cp_wait<1>();
    __syncthreads();

    // GEMM-S: scores[64 x 128] = Q @ Kchunk^T ; warp wid owns 16 s-columns
    float c[4][2][4];
#pragma unroll
    for (int i = 0; i < 4; i++)
#pragma unroll
        for (int j = 0; j < 2; j++)
#pragma unroll
            for (int k = 0; k < 4; k++) c[i][j][k] = 0.0f;

#pragma unroll
    for (int kst = 0; kst < 8; kst++) {
        int kk = kst * 8 + cq;
        uint32_t a[4][4], b[2][2];
#pragma unroll
        for (int mf = 0; mf < 4; mf++) {
            int r = mf * 16 + rb;
            a[mf][0] = f2tf(qs[r * 68 + kk]);
            a[mf][1] = f2tf(qs[(r + 8) * 68 + kk]);
            a[mf][2] = f2tf(qs[r * 68 + kk + 4]);
            a[mf][3] = f2tf(qs[(r + 8) * 68 + kk + 4]);
        }
#pragma unroll
        for (int nf = 0; nf < 2; nf++) {
            int sc = n0 + nf * 8 + rb;
            b[nf][0] = f2tf(ks[sc * 68 + kk]);
            b[nf][1] = f2tf(ks[sc * 68 + kk + 4]);
        }
#pragma unroll
        for (int mf = 0; mf < 4; mf++)
#pragma unroll
            for (int nf = 0; nf < 2; nf++)
                mma_tf32(c[mf][nf], a[mf], b[nf][0], b[nf][1]);
    }

    cp_wait<0>();       // V resident
    __syncthreads();    // all warps done reading qs/ks -> safe to alias ss

    // scores -> ss with mask add + clamp
#pragma unroll
    for (int mf = 0; mf < 4; mf++) {
        int r0 = mf * 16 + rb, r1 = r0 + 8;
#pragma unroll
        for (int nf = 0; nf < 2; nf++) {
            int col = n0 + nf * 8 + cq * 2;
            ss[r0 * 132 + col]     = fmaxf(c[mf][nf][0] + mk0[mf][nf].x, NEG_MAX);
            ss[r0 * 132 + col + 1] = fmaxf(c[mf][nf][1] + mk0[mf][nf].y, NEG_MAX);
            ss[r1 * 132 + col]     = fmaxf(c[mf][nf][2] + mk1[mf][nf].x, NEG_MAX);
            ss[r1 * 132 + col + 1] = fmaxf(c[mf][nf][3] + mk1[mf][nf].y, NEG_MAX);
        }
    }
    __syncthreads();

    // partial softmax: warp handles 8 rows; lane covers 4 columns each
    float* pmp = g_pm + (size_t)(h * NCH + cchunk) * M_ROWS;
    float* plp = g_pl + (size_t)(h * NCH + cchunk) * M_ROWS;
#pragma unroll
    for (int rr = 0; rr < 8; rr++) {
        int r = wid * 8 + rr;
        int base = r * 132 + lane * 4;
        float v0 = ss[base], v1 = ss[base + 1], v2 = ss[base + 2], v3 = ss[base + 3];
        float mx = fmaxf(fmaxf(v0, v1), fmaxf(v2, v3));
#pragma unroll
        for (int off = 16; off > 0; off >>= 1)
            mx = fmaxf(mx, __shfl_xor_sync(0xffffffffu, mx, off));
        float p0 = __expf(v0 - mx), p1 = __expf(v1 - mx);
        float p2 = __expf(v2 - mx), p3 = __expf(v3 - mx);
        float sum = (p0 + p1) + (p2 + p3);
#pragma unroll
        for (int off = 16; off > 0; off >>= 1)
            sum += __shfl_xor_sync(0xffffffffu, sum, off);
        ssb[base] = f2tf(p0); ssb[base + 1] = f2tf(p1);
        ssb[base + 2] = f2tf(p2); ssb[base + 3] = f2tf(p3);
        if (lane == 0) { pmp[r] = mx; plp[r] = sum; }
    }
    __syncthreads();

    // GEMM-O: opart[64 x 64] = probs[64 x 128] @ V[128 x 64]; warp wid owns 8 d-columns
    float o[4][4];
#pragma unroll
    for (int i = 0; i < 4; i++)
#pragma unroll
        for (int j = 0; j < 4; j++) o[i][j] = 0.0f;

    const int d0 = wid * 8;
#pragma unroll
    for (int kst = 0; kst < 16; kst++) {
        int kk = kst * 8 + cq;
        uint32_t a[4][4];
#pragma unroll
        for (int mf = 0; mf < 4; mf++) {
            int r = mf * 16 + rb;
            a[mf][0] = ssb[r * 132 + kk];
            a[mf][1] = ssb[(r + 8) * 132 + kk];
            a[mf][2] = ssb[r * 132 + kk + 4];
            a[mf][3] = ssb[(r + 8) * 132 + kk + 4];
        }
        uint32_t b0 = f2tf(vs[kk * 72 + d0 + rb]);
        uint32_t b1 = f2tf(vs[(kk + 4) * 72 + d0 + rb]);
#pragma unroll
        for (int mf = 0; mf < 4; mf++)
            mma_tf32(o[mf], a[mf], b0, b1);
    }

    float* op = g_opart + (size_t)(h * NCH + cchunk) * M_ROWS * HD;
#pragma unroll
    for (int mf = 0; mf < 4; mf++) {
        int r0 = mf * 16 + rb;
        int cd = d0 + cq * 2;
        *(float2*)(op + r0 * HD + cd)       = make_float2(o[mf][0], o[mf][1]);
        *(float2*)(op + (r0 + 8) * HD + cd) = make_float2(o[mf][2], o[mf][3]);
    }
}

// ---------------- combine partials + the 4 batch-local new KV positions ----------------
__global__ void __launch_bounds__(256) attn_combine(const float* __restrict__ mask)
{
    __shared__ float red[4][4][2];
    __shared__ float shm[4][32], shl[4][32], ew[4][32], esn[4][4];

    const int tid = threadIdx.x;
    const int rg = tid >> 6, g = tid & 63;
    const int R = blockIdx.x * 4 + rg;
    const int h = R >> 6, m = R & 63;
    const int b = m >> 2;
    const int lane = tid & 31;
    const int whalf = (tid >> 5) & 1;

    float qv = g_q[m * E_DIM + h * HD + g];
#pragma unroll
    for (int tp = 0; tp < 4; tp++) {
        float pv = qv * g_k[(b * 4 + tp) * E_DIM + h * HD + g];
#pragma unroll
        for (int off = 16; off > 0; off >>= 1)
            pv += __shfl_xor_sync(0xffffffffu, pv, off);
        if (lane == 0) red[rg][tp][whalf] = pv;
    }
    if (g < 32) {
        shm[rg][g] = g_pm[(size_t)(h * NCH + g) * M_ROWS + m];
        shl[rg][g] = g_pl[(size_t)(h * NCH + g) * M_ROWS + m];
    }
    __syncthreads();

    float sn[4];
#pragma unroll
    for (int tp = 0; tp < 4; tp++)
        sn[tp] = fmaxf(red[rg][tp][0] + red[rg][tp][1] + mask[m * S_LEN + P_LEN + tp], NEG_MAX);

    float M = NEG_MAX;
#pragma unroll
    for (int cc = 0; cc < 32; cc++) M = fmaxf(M, shm[rg][cc]);
#pragma unroll
    for (int tp = 0; tp < 4; tp++) M = fmaxf(M, sn[tp]);

    if (g < 32) ew[rg][g] = __expf(shm[rg][g] - M);
    if (g < 4)  esn[rg][g] = __expf(sn[g] - M);
    __syncthreads();

    float L = 0.0f;
#pragma unroll
    for (int cc = 0; cc < 32; cc++) L += shl[rg][cc] * ew[rg][cc];
#pragma unroll
    for (int tp = 0; tp < 4; tp++) L += esn[rg][tp];

    float o = 0.0f;
#pragma unroll 8
    for (int cc = 0; cc < 32; cc++)
        o += g_opart[((size_t)(h * NCH + cc) * M_ROWS + m) * HD + g] * ew[rg][cc];
#pragma unroll
    for (int tp = 0; tp < 4; tp++)
        o += esn[rg][tp] * g_v[(b * 4 + tp) * E_DIM + h * HD + g];

    g_attn[m * E_DIM + h * HD + g] = o / L;
}

// ---------------- launch ----------------
extern "C" void kernel_launch(void* const* d_in, const int* in_sizes, int n_in,
                              void* d_out, int out_size)
{
    const float* hs   = (const float*)d_in[0];
    const float* pk   = (const float*)d_in[1];
    const float* pv   = (const float*)d_in[2];
    const float* mask = (const float*)d_in[3];
    const float* Wq   = (const float*)d_in[4];
    const float* bq   = (const float*)d_in[5];
    const float* Wk   = (const float*)d_in[6];
    const float* bk   = (const float*)d_in[7];
    const float* Wv   = (const float*)d_in[8];
    const float* bv   = (const float*)d_in[9];
    const float* Wo   = (const float*)d_in[10];
    const float* bo   = (const float*)d_in[11];
    float* out = (float*)d_out;

    const int gemm_smem = 4 * 128 * 36 * 4;                     // 73728
    const int attn_smem = (64 * 68 + 128 * 68 + 128 * 72) * 4;  // 89088

    cudaFuncSetAttribute(gemm_w, cudaFuncAttributeMaxDynamicSharedMemorySize, gemm_smem);
    cudaFuncSetAttribute(attn_part, cudaFuncAttributeMaxDynamicSharedMemorySize, attn_smem);

    // QKV projections: split-K 2, 192 blocks
    gemm_w<<<dim3(32, 3, 2), 256, gemm_smem>>>(hs, Wq, Wk, Wv, 1024);
    reduce_qkv<<<384, 256>>>(bq, bk, bv);
    // attention over past cache (flash-decoding partials)
    attn_part<<<dim3(NCH, H_NUM), 256, attn_smem>>>(pk, pv, mask);
    // merge partials + new-token KV
    attn_combine<<<512, 256>>>(mask);
    // output projection: split-K 4, 128 blocks (A=nullptr -> g_attn selected device-side)
    gemm_w<<<dim3(32, 1, 4), 256, gemm_smem>>>(nullptr, Wo, Wo, Wo, 512);
    reduce_o<<<128, 256>>>(bo, out);
}

// round 6
// speedup vs baseline: 2.5583x; 1.0927x over previous
#include <cuda_runtime.h>
#include <cstdint>

#define E_DIM 2048
#define H_NUM 32
#define HD 64
#define P_LEN 4096
#define S_LEN 4100
#define M_ROWS 64
#define CH 128
#define NCH 32
#define APART_GRID 152
#define NEG_MAX (-3.4028234663852886e38f)

// ---------------- scratch (device globals: no allocs allowed) ----------------
__device__ __align__(256) float g_q[M_ROWS * E_DIM];
__device__ __align__(256) float g_k[M_ROWS * E_DIM];
__device__ __align__(256) float g_v[M_ROWS * E_DIM];
__device__ __align__(256) float g_attn[M_ROWS * E_DIM];
// opart layout: [m][h][cc][g]  (m*65536 + h*2048 + cc*64 + g)
__device__ __align__(256) float g_opart[M_ROWS * H_NUM * NCH * HD];
// pm/pl layout: [m][h][cc]     (m*1024 + h*32 + cc)
__device__ __align__(256) float g_pm[M_ROWS * H_NUM * NCH];
__device__ __align__(256) float g_pl[M_ROWS * H_NUM * NCH];
__device__ __align__(256) float g_pp[12 * M_ROWS * E_DIM];   // split-K partials

// ---------------- helpers ----------------
__device__ __forceinline__ uint32_t f2tf(float f) {
    uint32_t u;
    asm("cvt.rna.tf32.f32 %0, %1;" : "=r"(u) : "f"(f));
    return u;
}

__device__ __forceinline__ void mma_tf32(float* c, const uint32_t* a, uint32_t b0, uint32_t b1) {
    asm volatile(
        "mma.sync.aligned.m16n8k8.row.col.f32.tf32.tf32.f32 "
        "{%0,%1,%2,%3},{%4,%5,%6,%7},{%8,%9},{%0,%1,%2,%3};"
        : "+f"(c[0]), "+f"(c[1]), "+f"(c[2]), "+f"(c[3])
        : "r"(a[0]), "r"(a[1]), "r"(a[2]), "r"(a[3]), "r"(b0), "r"(b1));
}

__device__ __forceinline__ void cp16(float* smem_dst, const float* gsrc) {
    uint32_t s = (uint32_t)__cvta_generic_to_shared(smem_dst);
    asm volatile("cp.async.cg.shared.global [%0], [%1], 16;" :: "r"(s), "l"(gsrc));
}
__device__ __forceinline__ void cp_commit() {
    asm volatile("cp.async.commit_group;");
}
template<int N> __device__ __forceinline__ void cp_wait() {
    asm volatile("cp.async.wait_group %0;" :: "n"(N));
}

// ---------------- W-major split-K projection GEMM ----------------
// C[f, t] = sum_k W[f,k] * A[t,k]; W is the mma A-operand, tokens the B-operand.
// grid: (feature_tiles=32, n_mats, ksplit). partial slot = z*gridDim.y + y.
// A == nullptr selects g_attn (device-side).
__global__ void __launch_bounds__(256) gemm_w(
    const float* __restrict__ A,
    const float* __restrict__ W0, const float* __restrict__ W1, const float* __restrict__ W2,
    int kspan)
{
    extern __shared__ float sm[];
    const int STAGE = 128 * 36;

    if (A == nullptr) A = g_attn;
    const float* W = (blockIdx.y == 0) ? W0 : (blockIdx.y == 1) ? W1 : W2;
    const int fbase = blockIdx.x * 64;
    const int k0 = blockIdx.z * kspan;
    float* part = g_pp + (size_t)(blockIdx.z * gridDim.y + blockIdx.y) * (M_ROWS * E_DIM);

    const int tid = threadIdx.x;
    const int lane = tid & 31, wid = tid >> 5;
    const int rb = lane >> 2, cq = lane & 3;
    const int m0 = (wid >> 1) * 16;     // feature sub-tile
    const int n0 = (wid & 1) * 32;      // token sub-tile

    float c[4][4];
#pragma unroll
    for (int i = 0; i < 4; i++)
#pragma unroll
        for (int j = 0; j < 4; j++) c[i][j] = 0.0f;

    auto load_stage = [&](int buf, int kk0) {
        float* ws = sm + buf * STAGE;
        float* as = ws + 64 * 36;
        int row = tid >> 3, kc = tid & 7;
        cp16(ws + row * 36 + kc * 4,        W + (size_t)(fbase + row) * E_DIM + kk0 + kc * 4);
        cp16(ws + (row + 32) * 36 + kc * 4, W + (size_t)(fbase + row + 32) * E_DIM + kk0 + kc * 4);
        cp16(as + row * 36 + kc * 4,        A + (row) * E_DIM + kk0 + kc * 4);
        cp16(as + (row + 32) * 36 + kc * 4, A + (row + 32) * E_DIM + kk0 + kc * 4);
    };

#pragma unroll
    for (int s = 0; s < 3; s++) { load_stage(s, k0 + s * 32); cp_commit(); }

    const int NITER = kspan / 32;
    for (int it = 0; it < NITER; it++) {
        cp_wait<2>();
        __syncthreads();
        float* ws = sm + (it & 3) * STAGE;
        float* as = ws + 64 * 36;
#pragma unroll
        for (int ks = 0; ks < 4; ks++) {
            int kk = ks * 8 + cq;
            uint32_t a[4];
            a[0] = f2tf(ws[(m0 + rb) * 36 + kk]);
            a[1] = f2tf(ws[(m0 + 8 + rb) * 36 + kk]);
            a[2] = f2tf(ws[(m0 + rb) * 36 + kk + 4]);
            a[3] = f2tf(ws[(m0 + 8 + rb) * 36 + kk + 4]);
#pragma unroll
            for (int nf = 0; nf < 4; nf++) {
                int nn = n0 + nf * 8 + rb;
                uint32_t b0 = f2tf(as[nn * 36 + kk]);
                uint32_t b1 = f2tf(as[nn * 36 + kk + 4]);
                mma_tf32(c[nf], a, b0, b1);
            }
        }
        int nx = it + 3;
        if (nx < NITER) load_stage(nx & 3, k0 + nx * 32);
        cp_commit();
    }

    const int f = fbase + m0 + rb;
#pragma unroll
    for (int nf = 0; nf < 4; nf++) {
        int t0 = n0 + nf * 8 + cq * 2;
        part[t0 * E_DIM + f]           = c[nf][0];
        part[(t0 + 1) * E_DIM + f]     = c[nf][1];
        part[t0 * E_DIM + f + 8]       = c[nf][2];
        part[(t0 + 1) * E_DIM + f + 8] = c[nf][3];
    }
}

// ---------------- reduce split-K partials ----------------
// QKV: slots {mat, mat+3, mat+6, mat+9}, add bias, scale Q. grid 384x256 (float4)
__global__ void __launch_bounds__(256) reduce_qkv(
    const float* __restrict__ bq, const float* __restrict__ bk, const float* __restrict__ bv)
{
    int gid = blockIdx.x * 256 + threadIdx.x;    // 0..98303
    int mat = gid >> 15;
    int r = gid & 32767;
    int f4 = r & 511;
    const float4* pp = (const float4*)g_pp;
    float4 a = pp[(size_t)mat * 32768 + r];
    float4 b = pp[(size_t)(mat + 3) * 32768 + r];
    float4 c = pp[(size_t)(mat + 6) * 32768 + r];
    float4 d = pp[(size_t)(mat + 9) * 32768 + r];
    const float* bias = (mat == 0) ? bq : (mat == 1) ? bk : bv;
    float4 bb = ((const float4*)bias)[f4];
    float s = (mat == 0) ? 0.125f : 1.0f;
    float4 o;
    o.x = (a.x + b.x + c.x + d.x + bb.x) * s;
    o.y = (a.y + b.y + c.y + d.y + bb.y) * s;
    o.z = (a.z + b.z + c.z + d.z + bb.z) * s;
    o.w = (a.w + b.w + c.w + d.w + bb.w) * s;
    float* out = (mat == 0) ? g_q : (mat == 1) ? g_k : g_v;
    ((float4*)out)[r] = o;
}

// O-proj: slots 0..7, add bias, write d_out. grid 128x256
__global__ void __launch_bounds__(256) reduce_o(const float* __restrict__ bo, float* __restrict__ out)
{
    int r = blockIdx.x * 256 + threadIdx.x;      // 0..32767
    int f4 = r & 511;
    const float4* pp = (const float4*)g_pp;
    float4 bb = ((const float4*)bo)[f4];
    float ox = bb.x, oy = bb.y, oz = bb.z, ow = bb.w;
#pragma unroll
    for (int s = 0; s < 8; s++) {
        float4 a = pp[(size_t)s * 32768 + r];
        ox += a.x; oy += a.y; oz += a.z; ow += a.w;
    }
    ((float4*)out)[r] = make_float4(ox, oy, oz, ow);
}

// ---------------- attention over past cache: persistent, pipelined over chunks ----------------
// 152 blocks; each owns a contiguous range of items (item = h*32 + chunk).
// Double-buffered Q/K/V in smem, one cp.async group per item, wait_group(1) overlap.
__global__ void __launch_bounds__(256, 1) attn_part(
    const float* __restrict__ kpast, const float* __restrict__ vpast,
    const float* __restrict__ mask)
{
    extern __shared__ float sm[];
    float* qs = sm;                     // 2 x [64][68]
    float* ks = qs + 2 * 64 * 68;       // 2 x [128][68]
    float* vs = ks + 2 * 128 * 68;      // 2 x [128][72]
    float* ss = vs + 2 * 128 * 72;      // [64][132]
    uint32_t* ssb = (uint32_t*)ss;

    const int tid = threadIdx.x;
    const int lane = tid & 31, wid = tid >> 5;
    const int rb = lane >> 2, cq = lane & 3;
    const int n0 = wid * 16;
    const int d0 = wid * 8;

    const int bid = blockIdx.x;
    const int start = (bid * 1024) / APART_GRID;
    const int end = ((bid + 1) * 1024) / APART_GRID;
    if (start >= end) return;

    auto prefetch = [&](int item, int slot) {
        int h = item >> 5, c = item & 31, s0 = c * CH;
        float* qb = qs + slot * (64 * 68);
        float* kb = ks + slot * (128 * 68);
        float* vb = vs + slot * (128 * 72);
#pragma unroll
        for (int i = 0; i < 4; i++) {
            int cc = tid + i * 256;
            int m = cc >> 4, kc = cc & 15;
            cp16(qb + m * 68 + kc * 4, g_q + m * E_DIM + h * HD + kc * 4);
        }
#pragma unroll
        for (int i = 0; i < 8; i++) {
            int cc = tid + i * 256;
            int s = cc >> 4, kc = cc & 15;
            cp16(kb + s * 68 + kc * 4, kpast + ((size_t)h * P_LEN + s0 + s) * HD + kc * 4);
        }
#pragma unroll
        for (int i = 0; i < 8; i++) {
            int cc = tid + i * 256;
            int s = cc >> 4, kc = cc & 15;
            cp16(vb + s * 72 + kc * 4, vpast + ((size_t)h * P_LEN + s0 + s) * HD + kc * 4);
        }
        cp_commit();
    };

    prefetch(start, start & 1);

    for (int it = start; it < end; it++) {
        const int h = it >> 5, c = it & 31, s0 = c * CH;
        const int slot = it & 1;
        float* qb = qs + slot * (64 * 68);
        float* kb = ks + slot * (128 * 68);
        float* vb = vs + slot * (128 * 72);

        // mask values for this item (registers; overlaps with pending cp.async)
        float2 mk0[4][2], mk1[4][2];
#pragma unroll
        for (int mf = 0; mf < 4; mf++) {
            int r0 = mf * 16 + rb, r1 = r0 + 8;
#pragma unroll
            for (int nf = 0; nf < 2; nf++) {
                int sg = s0 + n0 + nf * 8 + cq * 2;
                mk0[mf][nf] = *(const float2*)(mask + r0 * S_LEN + sg);
                mk1[mf][nf] = *(const float2*)(mask + r1 * S_LEN + sg);
            }
        }

        if (it + 1 < end) { prefetch(it + 1, (it + 1) & 1); cp_wait<1>(); }
        else              { cp_wait<0>(); }
        __syncthreads();

        // GEMM-S: scores[64 x 128] = Q @ Kchunk^T ; warp wid owns 16 s-columns
        float cacc[4][2][4];
#pragma unroll
        for (int i = 0; i < 4; i++)
#pragma unroll
            for (int j = 0; j < 2; j++)
#pragma unroll
                for (int k = 0; k < 4; k++) cacc[i][j][k] = 0.0f;

#pragma unroll
        for (int kst = 0; kst < 8; kst++) {
            int kk = kst * 8 + cq;
            uint32_t a[4][4], b[2][2];
#pragma unroll
            for (int mf = 0; mf < 4; mf++) {
                int r = mf * 16 + rb;
                a[mf][0] = f2tf(qb[r * 68 + kk]);
                a[mf][1] = f2tf(qb[(r + 8) * 68 + kk]);
                a[mf][2] = f2tf(qb[r * 68 + kk + 4]);
                a[mf][3] = f2tf(qb[(r + 8) * 68 + kk + 4]);
            }
#pragma unroll
            for (int nf = 0; nf < 2; nf++) {
                int sc = n0 + nf * 8 + rb;
                b[nf][0] = f2tf(kb[sc * 68 + kk]);
                b[nf][1] = f2tf(kb[sc * 68 + kk + 4]);
            }
#pragma unroll
            for (int mf = 0; mf < 4; mf++)
#pragma unroll
                for (int nf = 0; nf < 2; nf++)
                    mma_tf32(cacc[mf][nf], a[mf], b[nf][0], b[nf][1]);
        }

        // scores -> ss with mask add + clamp
#pragma unroll
        for (int mf = 0; mf < 4; mf++) {
            int r0 = mf * 16 + rb, r1 = r0 + 8;
#pragma unroll
            for (int nf = 0; nf < 2; nf++) {
                int col = n0 + nf * 8 + cq * 2;
                ss[r0 * 132 + col]     = fmaxf(cacc[mf][nf][0] + mk0[mf][nf].x, NEG_MAX);
                ss[r0 * 132 + col + 1] = fmaxf(cacc[mf][nf][1] + mk0[mf][nf].y, NEG_MAX);
                ss[r1 * 132 + col]     = fmaxf(cacc[mf][nf][2] + mk1[mf][nf].x, NEG_MAX);
                ss[r1 * 132 + col + 1] = fmaxf(cacc[mf][nf][3] + mk1[mf][nf].y, NEG_MAX);
            }
        }
        __syncthreads();

        // partial softmax: warp handles 8 rows; lane covers 4 columns each
#pragma unroll
        for (int rr = 0; rr < 8; rr++) {
            int r = wid * 8 + rr;
            int base = r * 132 + lane * 4;
            float v0 = ss[base], v1 = ss[base + 1], v2 = ss[base + 2], v3 = ss[base + 3];
            float mx = fmaxf(fmaxf(v0, v1), fmaxf(v2, v3));
#pragma unroll
            for (int off = 16; off > 0; off >>= 1)
                mx = fmaxf(mx, __shfl_xor_sync(0xffffffffu, mx, off));
            float p0 = __expf(v0 - mx), p1 = __expf(v1 - mx);
            float p2 = __expf(v2 - mx), p3 = __expf(v3 - mx);
            float sum = (p0 + p1) + (p2 + p3);
#pragma unroll
            for (int off = 16; off > 0; off >>= 1)
                sum += __shfl_xor_sync(0xffffffffu, sum, off);
            ssb[base] = f2tf(p0); ssb[base + 1] = f2tf(p1);
            ssb[base + 2] = f2tf(p2); ssb[base + 3] = f2tf(p3);
            if (lane == 0) {
                g_pm[r * 1024 + h * NCH + c] = mx;
                g_pl[r * 1024 + h * NCH + c] = sum;
            }
        }
        __syncthreads();

        // GEMM-O: opart[64 x 64] = probs[64 x 128] @ V[128 x 64]; warp wid owns 8 d-cols
        float o[4][4];
#pragma unroll
        for (int i = 0; i < 4; i++)
#pragma unroll
            for (int j = 0; j < 4; j++) o[i][j] = 0.0f;

#pragma unroll
        for (int kst = 0; kst < 16; kst++) {
            int kk = kst * 8 + cq;
            uint32_t a[4][4];
#pragma unroll
            for (int mf = 0; mf < 4; mf++) {
                int r = mf * 16 + rb;
                a[mf][0] = ssb[r * 132 + kk];
                a[mf][1] = ssb[(r + 8) * 132 + kk];
                a[mf][2] = ssb[r * 132 + kk + 4];
                a[mf][3] = ssb[(r + 8) * 132 + kk + 4];
            }
            uint32_t b0 = f2tf(vb[kk * 72 + d0 + rb]);
            uint32_t b1 = f2tf(vb[(kk + 4) * 72 + d0 + rb]);
#pragma unroll
            for (int mf = 0; mf < 4; mf++)
                mma_tf32(o[mf], a[mf], b0, b1);
        }

        // store opart [m][h][cc][g]
#pragma unroll
        for (int mf = 0; mf < 4; mf++) {
            int r0 = mf * 16 + rb;
            int cd = d0 + cq * 2;
            *(float2*)(g_opart + (size_t)r0 * 65536 + h * 2048 + c * 64 + cd)
                = make_float2(o[mf][0], o[mf][1]);
            *(float2*)(g_opart + (size_t)(r0 + 8) * 65536 + h * 2048 + c * 64 + cd)
                = make_float2(o[mf][2], o[mf][3]);
        }
        __syncthreads();
    }
}

// ---------------- combine partials + the 4 batch-local new KV positions ----------------
// warp per (h,m) row; grid 256 x 8 warps covers 2048 rows. Register/shuffle-only stats.
__global__ void __launch_bounds__(256) attn_combine(const float* __restrict__ mask)
{
    const int tid = threadIdx.x;
    const int lane = tid & 31;
    const int rg = tid >> 5;
    const int R = blockIdx.x * 8 + rg;
    const int h = R >> 6, m = R & 63, b = m >> 2;

    float2 q2 = *(const float2*)(g_q + m * E_DIM + h * HD + lane * 2);
    float sn[4];
#pragma unroll
    for (int tp = 0; tp < 4; tp++) {
        float2 k2 = *(const float2*)(g_k + (b * 4 + tp) * E_DIM + h * HD + lane * 2);
        float pv = q2.x * k2.x + q2.y * k2.y;
#pragma unroll
        for (int off = 16; off > 0; off >>= 1)
            pv += __shfl_xor_sync(0xffffffffu, pv, off);
        sn[tp] = fmaxf(pv + mask[m * S_LEN + P_LEN + tp], NEG_MAX);
    }

    float pmL = g_pm[m * 1024 + h * NCH + lane];
    float plL = g_pl[m * 1024 + h * NCH + lane];
    float M = pmL;
#pragma unroll
    for (int off = 16; off > 0; off >>= 1)
        M = fmaxf(M, __shfl_xor_sync(0xffffffffu, M, off));
#pragma unroll
    for (int tp = 0; tp < 4; tp++) M = fmaxf(M, sn[tp]);

    float eL = __expf(pmL - M);
    float L = plL * eL;
#pragma unroll
    for (int off = 16; off > 0; off >>= 1)
        L += __shfl_xor_sync(0xffffffffu, L, off);
    float esn[4];
#pragma unroll
    for (int tp = 0; tp < 4; tp++) { esn[tp] = __expf(sn[tp] - M); L += esn[tp]; }

    const float* opr = g_opart + (size_t)m * 65536 + h * 2048 + lane * 2;
    float ox = 0.0f, oy = 0.0f;
#pragma unroll
    for (int cc = 0; cc < 32; cc++) {
        float w = __shfl_sync(0xffffffffu, eL, cc);
        float2 p = *(const float2*)(opr + cc * 64);
        ox += p.x * w; oy += p.y * w;
    }
#pragma unroll
    for (int tp = 0; tp < 4; tp++) {
        float2 v2 = *(const float2*)(g_v + (b * 4 + tp) * E_DIM + h * HD + lane * 2);
        ox += esn[tp] * v2.x; oy += esn[tp] * v2.y;
    }
    float inv = 1.0f / L;
    *(float2*)(g_attn + m * E_DIM + h * HD + lane * 2) = make_float2(ox * inv, oy * inv);
}

// ---------------- launch ----------------
extern "C" void kernel_launch(void* const* d_in, const int* in_sizes, int n_in,
                              void* d_out, int out_size)
{
    const float* hs   = (const float*)d_in[0];
    const float* pk   = (const float*)d_in[1];
    const float* pv   = (const float*)d_in[2];
    const float* mask = (const float*)d_in[3];
    const float* Wq   = (const float*)d_in[4];
    const float* bq   = (const float*)d_in[5];
    const float* Wk   = (const float*)d_in[6];
    const float* bk   = (const float*)d_in[7];
    const float* Wv   = (const float*)d_in[8];
    const float* bv   = (const float*)d_in[9];
    const float* Wo   = (const float*)d_in[10];
    const float* bo   = (const float*)d_in[11];
    float* out = (float*)d_out;

    const int gemm_smem = 4 * 128 * 36 * 4;                               // 73728
    const int attn_smem = (2 * 64 * 68 + 2 * 128 * 68 + 2 * 128 * 72 + 64 * 132) * 4; // 211968

    cudaFuncSetAttribute(gemm_w, cudaFuncAttributeMaxDynamicSharedMemorySize, gemm_smem);
    cudaFuncSetAttribute(attn_part, cudaFuncAttributeMaxDynamicSharedMemorySize, attn_smem);

    // QKV projections: split-K 4, 384 blocks
    gemm_w<<<dim3(32, 3, 4), 256, gemm_smem>>>(hs, Wq, Wk, Wv, 512);
    reduce_qkv<<<384, 256>>>(bq, bk, bv);
    // attention over past cache (persistent flash-decoding, pipelined)
    attn_part<<<APART_GRID, 256, attn_smem>>>(pk, pv, mask);
    // merge partials + new-token KV
    attn_combine<<<256, 256>>>(mask);
    // output projection: split-K 8, 256 blocks (A=nullptr -> g_attn device-side)
    gemm_w<<<dim3(32, 1, 8), 256, gemm_smem>>>(nullptr, Wo, Wo, Wo, 256);
    reduce_o<<<128, 256>>>(bo, out);
}